// round 8
// baseline (speedup 1.0000x reference)
#include <cuda_runtime.h>
#include <cuda_bf16.h>
#include <math.h>
#include <stdint.h>

// Problem constants (fixed shapes)
#define NB 2
#define NS 2048
#define ND 4096
#define NH 32
#define NHD 128
#define NAL 10

// ---------------------------------------------------------------------------
// Scratch (__device__ globals — allocation-free rule)
// ---------------------------------------------------------------------------
static __device__ __align__(256) float g_Q[(size_t)NB * NS * ND];
static __device__ __align__(256) float g_K[(size_t)NB * NS * ND];
static __device__ __align__(256) float g_AO[(size_t)NB * NS * ND];
static __device__ __align__(256) float g_scores[(size_t)NB * NH * NS * NS]; // 1 GB
static __device__ float g_ak[NAL * ND];
static __device__ float g_av[NAL * ND];

static __device__ __align__(256) __nv_bfloat16 g_xh[(size_t)NB * NS * ND];
static __device__ __align__(256) __nv_bfloat16 g_xl[(size_t)NB * NS * ND];
static __device__ __align__(256) __nv_bfloat16 g_Qh[(size_t)NB * NS * ND];
static __device__ __align__(256) __nv_bfloat16 g_Ql[(size_t)NB * NS * ND];
static __device__ __align__(256) __nv_bfloat16 g_Kh[(size_t)NB * NS * ND];
static __device__ __align__(256) __nv_bfloat16 g_Kl[(size_t)NB * NS * ND];
static __device__ __align__(256) __nv_bfloat16 g_Vth[(size_t)NB * NS * ND]; // V^T: [b][h][d][s]
static __device__ __align__(256) __nv_bfloat16 g_Vtl[(size_t)NB * NS * ND];
static __device__ __align__(256) __nv_bfloat16 g_Ph[(size_t)NB * NH * NS * NS];
static __device__ __align__(256) __nv_bfloat16 g_Pl[(size_t)NB * NH * NS * NS];
static __device__ __align__(256) __nv_bfloat16 g_AOh[(size_t)NB * NS * ND];
static __device__ __align__(256) __nv_bfloat16 g_AOl[(size_t)NB * NS * ND];
static __device__ __align__(256) __nv_bfloat16 g_wqh[(size_t)ND * ND];
static __device__ __align__(256) __nv_bfloat16 g_wql[(size_t)ND * ND];
static __device__ __align__(256) __nv_bfloat16 g_wkh[(size_t)ND * ND];
static __device__ __align__(256) __nv_bfloat16 g_wkl[(size_t)ND * ND];
static __device__ __align__(256) __nv_bfloat16 g_wvh[(size_t)ND * ND];
static __device__ __align__(256) __nv_bfloat16 g_wvl[(size_t)ND * ND];
static __device__ __align__(256) __nv_bfloat16 g_woh[(size_t)ND * ND];
static __device__ __align__(256) __nv_bfloat16 g_wol[(size_t)ND * ND];

// ---------------------------------------------------------------------------
// Helpers
// ---------------------------------------------------------------------------
__device__ __forceinline__ void split2(float v, __nv_bfloat16& h, __nv_bfloat16& l) {
    h = __float2bfloat16(v);
    l = __float2bfloat16(v - __bfloat162float(h));
}
__device__ __forceinline__ void cpasync16(uint32_t dst, const void* src) {
    asm volatile("cp.async.cg.shared.global [%0], [%1], 16;\n" :: "r"(dst), "l"(src));
}
__device__ __forceinline__ void cp_commit() {
    asm volatile("cp.async.commit_group;\n" ::: "memory");
}
__device__ __forceinline__ void cp_wait1() {
    asm volatile("cp.async.wait_group 1;\n" ::: "memory");
}
__device__ __forceinline__ void ldsm4(uint32_t* r, uint32_t addr) {
    asm volatile("ldmatrix.sync.aligned.m8n8.x4.shared.b16 {%0,%1,%2,%3}, [%4];\n"
                 : "=r"(r[0]), "=r"(r[1]), "=r"(r[2]), "=r"(r[3]) : "r"(addr));
}
__device__ __forceinline__ void mma16816(float* c, const uint32_t* a, const uint32_t* b) {
    asm volatile(
        "mma.sync.aligned.m16n8k16.row.col.f32.bf16.bf16.f32 "
        "{%0,%1,%2,%3},{%4,%5,%6,%7},{%8,%9},{%0,%1,%2,%3};\n"
        : "+f"(c[0]), "+f"(c[1]), "+f"(c[2]), "+f"(c[3])
        : "r"(a[0]), "r"(a[1]), "r"(a[2]), "r"(a[3]), "r"(b[0]), "r"(b[1]));
}

// ---------------------------------------------------------------------------
// Split-bf16 tensor-core GEMM.  C[m][n] = sum_k A[m][k]*B[n][k]
// CTA tile BM x BN, 8 warps (WR x WC) of 64x64 each, BK=16,
// 3-stage cp.async pipeline (wait_group 1), dynamic smem = 3*64*(BM+BN) B.
// 3 bf16 MMA passes: Ahi*Bhi + Ahi*Blo + Alo*Bhi (fp32 accum).
// EPI 0: C fp32.  EPI 1: C = acc*alpha + mask.  EPI 2: V^T hi/lo split write.
// ---------------------------------------------------------------------------
template <int BM, int BN, int WC, int EPI>
__global__ __launch_bounds__(256, 1) void mma_gemm(
    const __nv_bfloat16* __restrict__ Ah, const __nv_bfloat16* __restrict__ Al,
    const __nv_bfloat16* __restrict__ Bh, const __nv_bfloat16* __restrict__ Bl,
    float* __restrict__ C,
    int K, int lda, int ldb, int ldc, int Hdiv,
    long long sAb, long long sAh_, long long sBb, long long sBh_,
    long long sCb, long long sCh_,
    float alpha, const float* __restrict__ mask,
    __nv_bfloat16* __restrict__ Chi, __nv_bfloat16* __restrict__ Clo)
{
    extern __shared__ __align__(16) __nv_bfloat16 smdyn[];
    constexpr int STAGE = 64 * (BM + BN);   // bytes per stage (A hi/lo + B hi/lo)

    const int t = threadIdx.x;
    const int lane = t & 31;
    const int wid = t >> 5;
    const int warp_m = wid / WC;
    const int warp_n = wid % WC;

    const int z = blockIdx.z;
    const int zb = z / Hdiv;
    const int zh = z % Hdiv;
    const __nv_bfloat16* pAh = Ah + zb * sAb + zh * sAh_;
    const __nv_bfloat16* pAl = Al + zb * sAb + zh * sAh_;
    const __nv_bfloat16* pBh = Bh + zb * sBb + zh * sBh_;
    const __nv_bfloat16* pBl = Bl + zb * sBb + zh * sBh_;
    float* pC = C + zb * sCb + zh * sCh_;

    const int bm = blockIdx.y * BM;
    const int bn = blockIdx.x * BN;

    const uint32_t smem0 = (uint32_t)__cvta_generic_to_shared(smdyn);

    // ldmatrix per-lane offsets (row stride 32B = 16 bf16)
    const uint32_t aoff = (uint32_t)((lane & 15) * 32 + (lane >> 4) * 16);
    const int rB = (lane & 7) | ((lane & 16) >> 1);
    const uint32_t boff = (uint32_t)(rB * 32 + (lane & 8) * 2);

    const int T = K / 16;

    // --- stage loader ---
    auto load_stage = [&](int s) {
        if (s < T) {
            const int kk = s * 16;
            const uint32_t sbase = smem0 + (uint32_t)((s % 3) * STAGE);
#pragma unroll
            for (int i = t; i < BM * 2; i += 256) {
                const int row = i >> 1;
                const int half = (i & 1) * 8;
                const uint32_t d = sbase + (uint32_t)(row * 32 + half * 2);
                const long long go = (long long)(bm + row) * lda + kk + half;
                cpasync16(d, pAh + go);
                cpasync16(d + BM * 32, pAl + go);
            }
#pragma unroll
            for (int i = t; i < BN * 2; i += 256) {
                const int row = i >> 1;
                const int half = (i & 1) * 8;
                const uint32_t d = sbase + (uint32_t)(2 * BM * 32 + row * 32 + half * 2);
                const long long go = (long long)(bn + row) * ldb + kk + half;
                cpasync16(d, pBh + go);
                cpasync16(d + BN * 32, pBl + go);
            }
        }
        cp_commit();
    };

    float c[4][8][4];
#pragma unroll
    for (int i = 0; i < 4; i++)
#pragma unroll
        for (int j = 0; j < 8; j++)
#pragma unroll
            for (int r = 0; r < 4; r++) c[i][j][r] = 0.0f;

    load_stage(0);
    load_stage(1);

    for (int s = 0; s < T; s++) {
        cp_wait1();
        __syncthreads();
        load_stage(s + 2);

        const uint32_t sbase = smem0 + (uint32_t)((s % 3) * STAGE);
        const uint32_t aA  = sbase + (uint32_t)(warp_m * 64 * 32) + aoff;
        const uint32_t aAl = aA + BM * 32;
        const uint32_t aB  = sbase + (uint32_t)(2 * BM * 32 + warp_n * 64 * 32) + boff;
        const uint32_t aBl = aB + BN * 32;

        uint32_t ah[4][4], al_[4][4], bh[4][4], bl[4][4];
#pragma unroll
        for (int mf = 0; mf < 4; mf++) ldsm4(ah[mf], aA + mf * 512);
#pragma unroll
        for (int nb = 0; nb < 4; nb++) ldsm4(bh[nb], aB + nb * 512);

        // pass 1: Ahi * Bhi
#pragma unroll
        for (int mf = 0; mf < 4; mf++)
#pragma unroll
            for (int nf = 0; nf < 8; nf++)
                mma16816(c[mf][nf], ah[mf], &bh[nf >> 1][(nf & 1) * 2]);

#pragma unroll
        for (int nb = 0; nb < 4; nb++) ldsm4(bl[nb], aBl + nb * 512);
        // pass 2: Ahi * Blo
#pragma unroll
        for (int mf = 0; mf < 4; mf++)
#pragma unroll
            for (int nf = 0; nf < 8; nf++)
                mma16816(c[mf][nf], ah[mf], &bl[nf >> 1][(nf & 1) * 2]);

#pragma unroll
        for (int mf = 0; mf < 4; mf++) ldsm4(al_[mf], aAl + mf * 512);
        // pass 3: Alo * Bhi
#pragma unroll
        for (int mf = 0; mf < 4; mf++)
#pragma unroll
            for (int nf = 0; nf < 8; nf++)
                mma16816(c[mf][nf], al_[mf], &bh[nf >> 1][(nf & 1) * 2]);
    }

    // --- epilogue ---
    const int gq = lane >> 2;
    const int tg = lane & 3;
#pragma unroll
    for (int mf = 0; mf < 4; mf++) {
#pragma unroll
        for (int nf = 0; nf < 8; nf++) {
            const int r0 = bm + warp_m * 64 + mf * 16 + gq;
            const int c0 = bn + warp_n * 64 + nf * 8 + tg * 2;
            float* cc = c[mf][nf];
            if (EPI == 0) {
                *(float2*)&pC[(long long)r0 * ldc + c0] = make_float2(cc[0], cc[1]);
                *(float2*)&pC[(long long)(r0 + 8) * ldc + c0] = make_float2(cc[2], cc[3]);
            } else if (EPI == 1) {
                float2 m0 = *(const float2*)&mask[(long long)r0 * NS + c0];
                float2 m1 = *(const float2*)&mask[(long long)(r0 + 8) * NS + c0];
                *(float2*)&pC[(long long)r0 * ldc + c0] =
                    make_float2(cc[0] * alpha + m0.x, cc[1] * alpha + m0.y);
                *(float2*)&pC[(long long)(r0 + 8) * ldc + c0] =
                    make_float2(cc[2] * alpha + m1.x, cc[3] * alpha + m1.y);
            } else { // EPI == 2: V^T hi/lo   Vt[((b*NH+h)*NHD+dc)*NS + s]
#pragma unroll
                for (int q = 0; q < 4; q++) {
                    const int m = r0 + (q >> 1) * 8;
                    const int n = c0 + (q & 1);
                    const int b = m >> 11, sdx = m & 2047;
                    const int h = n >> 7, dc = n & 127;
                    const long long idx =
                        (((long long)(b * NH + h)) * NHD + dc) * NS + sdx;
                    __nv_bfloat16 hb, lb;
                    split2(cc[q], hb, lb);
                    Chi[idx] = hb;
                    Clo[idx] = lb;
                }
            }
        }
    }
}

// ---------------------------------------------------------------------------
// Elementwise fp32 -> bf16 hi/lo split
// ---------------------------------------------------------------------------
__global__ void split_kernel(const float* __restrict__ src,
                             __nv_bfloat16* __restrict__ h,
                             __nv_bfloat16* __restrict__ l, long long n)
{
    long long i = ((long long)blockIdx.x * blockDim.x + threadIdx.x) * 4;
    if (i >= n) return;
    float4 v = *(const float4*)(src + i);
    __nv_bfloat16 hh[4], ll[4];
    split2(v.x, hh[0], ll[0]);
    split2(v.y, hh[1], ll[1]);
    split2(v.z, hh[2], ll[2]);
    split2(v.w, hh[3], ll[3]);
#pragma unroll
    for (int k = 0; k < 4; k++) { h[i + k] = hh[k]; l[i + k] = ll[k]; }
}

// ---------------------------------------------------------------------------
// Weight transpose + split: Wt[n][k] = W[k][n]
// ---------------------------------------------------------------------------
__global__ void wsplit_t_kernel(const float* __restrict__ W,
                                __nv_bfloat16* __restrict__ Th,
                                __nv_bfloat16* __restrict__ Tl)
{
    __shared__ float tile[32][33];
    const int n0 = blockIdx.x * 32, k0 = blockIdx.y * 32;
    const int tx = threadIdx.x, ty = threadIdx.y;
#pragma unroll
    for (int i = 0; i < 4; i++)
        tile[ty + 8 * i][tx] = W[(long long)(k0 + ty + 8 * i) * ND + n0 + tx];
    __syncthreads();
#pragma unroll
    for (int i = 0; i < 4; i++) {
        float v = tile[tx][ty + 8 * i];
        long long o = (long long)(n0 + ty + 8 * i) * ND + k0 + tx;
        __nv_bfloat16 hb, lb;
        split2(v, hb, lb);
        Th[o] = hb;
        Tl[o] = lb;
    }
}

// ---------------------------------------------------------------------------
// RoPE in-place fp32 + bf16 hi/lo outputs
// ---------------------------------------------------------------------------
__global__ void rope_qk_kernel(float* __restrict__ Q, float* __restrict__ K,
                               const float* __restrict__ cosT,
                               const float* __restrict__ sinT,
                               __nv_bfloat16* __restrict__ Qh, __nv_bfloat16* __restrict__ Ql,
                               __nv_bfloat16* __restrict__ Kh, __nv_bfloat16* __restrict__ Kl)
{
    long long idx = (long long)blockIdx.x * blockDim.x + threadIdx.x;
    const long long total = (long long)NB * NS * NH * (NHD / 2);
    if (idx >= total) return;
    int d2 = (int)(idx & (NHD / 2 - 1));
    long long r = idx >> 6;
    int h = (int)(r & (NH - 1));
    r >>= 5;
    int s = (int)(r & (NS - 1));
    int b = (int)(r >> 11);

    float cv = cosT[s * (NHD / 2) + d2];
    float sn = sinT[s * (NHD / 2) + d2];
    long long off = ((((long long)b * NS + s) * NH + h) * NHD) + 2 * d2;

    float2 q = *(float2*)(Q + off);
    float2 k = *(float2*)(K + off);
    float2 qo, ko;
    qo.x = q.x * cv - q.y * sn;
    qo.y = q.x * sn + q.y * cv;
    ko.x = k.x * cv - k.y * sn;
    ko.y = k.x * sn + k.y * cv;
    *(float2*)(Q + off) = qo;
    *(float2*)(K + off) = ko;

    __nv_bfloat16 hb, lb;
    split2(qo.x, hb, lb); Qh[off] = hb; Ql[off] = lb;
    split2(qo.y, hb, lb); Qh[off + 1] = hb; Ql[off + 1] = lb;
    split2(ko.x, hb, lb); Kh[off] = hb; Kl[off] = lb;
    split2(ko.y, hb, lb); Kh[off + 1] = hb; Kl[off + 1] = lb;
}

// ---------------------------------------------------------------------------
// Adapter projections (tiny fp32)
// ---------------------------------------------------------------------------
__global__ void adapter_gemm_kernel(const float* __restrict__ adapter,
                                    const float* __restrict__ Wk,
                                    const float* __restrict__ Wv,
                                    float* __restrict__ ak,
                                    float* __restrict__ av)
{
    const int n = blockIdx.x * 256 + threadIdx.x;
    __shared__ float a_sh[NAL][64];
    float accK[NAL], accV[NAL];
#pragma unroll
    for (int r = 0; r < NAL; r++) { accK[r] = 0.f; accV[r] = 0.f; }

    for (int k0 = 0; k0 < ND; k0 += 64) {
        for (int idx = threadIdx.x; idx < NAL * 64; idx += 256) {
            int r = idx / 64, cix = idx % 64;
            a_sh[r][cix] = adapter[r * ND + k0 + cix];
        }
        __syncthreads();
        for (int kc = 0; kc < 64; kc++) {
            float bk = Wk[(long long)(k0 + kc) * ND + n];
            float bv = Wv[(long long)(k0 + kc) * ND + n];
#pragma unroll
            for (int r = 0; r < NAL; r++) {
                accK[r] = fmaf(a_sh[r][kc], bk, accK[r]);
                accV[r] = fmaf(a_sh[r][kc], bv, accV[r]);
            }
        }
        __syncthreads();
    }
#pragma unroll
    for (int r = 0; r < NAL; r++) {
        ak[r * ND + n] = accK[r];
        av[r * ND + n] = accV[r];
    }
}

// ---------------------------------------------------------------------------
// Row softmax -> bf16 hi/lo P
// ---------------------------------------------------------------------------
__global__ void softmax_rows_kernel(const float* __restrict__ sc,
                                    __nv_bfloat16* __restrict__ ph,
                                    __nv_bfloat16* __restrict__ pl)
{
    long long row = blockIdx.x;
    const float* p = sc + row * (long long)NS;
    const int t = threadIdx.x;

    float v[8];
#pragma unroll
    for (int i = 0; i < 8; i++) v[i] = p[t + i * 256];

    float m = -1e30f;
#pragma unroll
    for (int i = 0; i < 8; i++) m = fmaxf(m, v[i]);

    __shared__ float red[256];
    red[t] = m;
    __syncthreads();
    for (int s = 128; s > 0; s >>= 1) {
        if (t < s) red[t] = fmaxf(red[t], red[t + s]);
        __syncthreads();
    }
    m = red[0];
    __syncthreads();

    float sum = 0.f;
#pragma unroll
    for (int i = 0; i < 8; i++) {
        v[i] = __expf(v[i] - m);
        sum += v[i];
    }
    red[t] = sum;
    __syncthreads();
    for (int s = 128; s > 0; s >>= 1) {
        if (t < s) red[t] += red[t + s];
        __syncthreads();
    }
    const float inv = 1.0f / red[0];

    long long base = row * (long long)NS;
#pragma unroll
    for (int i = 0; i < 8; i++) {
        float pv = v[i] * inv;
        __nv_bfloat16 hb, lb;
        split2(pv, hb, lb);
        ph[base + t + i * 256] = hb;
        pl[base + t + i * 256] = lb;
    }
}

// ---------------------------------------------------------------------------
// Adapter attention add (gated), fp32
// ---------------------------------------------------------------------------
__global__ void adapter_attn_kernel(float* __restrict__ AO,
                                    const float* __restrict__ Q,
                                    const float* __restrict__ ak,
                                    const float* __restrict__ av,
                                    const float* __restrict__ gate)
{
    const int h = blockIdx.y;
    const int b = blockIdx.z;
    const int lane = threadIdx.x & 31;
    const int w = threadIdx.x >> 5;
    const int q = blockIdx.x * 8 + w;
    const float inv_sqrt = 0.08838834764831845f;

    const float* qp = Q + (((long long)(b * NS + q)) * NH + h) * NHD;
    float qv[4];
#pragma unroll
    for (int i = 0; i < 4; i++) qv[i] = qp[lane + 32 * i];

    float sc[NAL];
#pragma unroll
    for (int j = 0; j < NAL; j++) {
        const float* akp = ak + j * ND + h * NHD;
        float s = 0.f;
#pragma unroll
        for (int i = 0; i < 4; i++) s = fmaf(qv[i], akp[lane + 32 * i], s);
#pragma unroll
        for (int off = 16; off > 0; off >>= 1)
            s += __shfl_xor_sync(0xFFFFFFFFu, s, off);
        sc[j] = s * inv_sqrt;
    }

    float m = sc[0];
#pragma unroll
    for (int j = 1; j < NAL; j++) m = fmaxf(m, sc[j]);
    float sum = 0.f;
#pragma unroll
    for (int j = 0; j < NAL; j++) {
        sc[j] = __expf(sc[j] - m);
        sum += sc[j];
    }
    const float g = gate[h] / sum;

    float o[4] = {0.f, 0.f, 0.f, 0.f};
#pragma unroll
    for (int j = 0; j < NAL; j++) {
        const float* avp = av + j * ND + h * NHD;
#pragma unroll
        for (int i = 0; i < 4; i++) o[i] = fmaf(sc[j], avp[lane + 32 * i], o[i]);
    }

    float* aop = AO + (((long long)(b * NS + q)) * NH + h) * NHD;
#pragma unroll
    for (int i = 0; i < 4; i++) aop[lane + 32 * i] += g * o[i];
}

// ---------------------------------------------------------------------------
// Launch sequence
// ---------------------------------------------------------------------------
extern "C" void kernel_launch(void* const* d_in, const int* in_sizes, int n_in,
                              void* d_out, int out_size)
{
    const float* x       = (const float*)d_in[0];
    const float* cosT    = (const float*)d_in[1];
    const float* sinT    = (const float*)d_in[2];
    const float* mask    = (const float*)d_in[3];
    const float* wq      = (const float*)d_in[4];
    const float* wk      = (const float*)d_in[5];
    const float* wv      = (const float*)d_in[6];
    const float* wo      = (const float*)d_in[7];
    const float* gate    = (const float*)d_in[8];
    const float* adapter = (const float*)d_in[9];
    float* out = (float*)d_out;

    float *Qp, *Kp, *AOp, *Sc, *akp, *avp;
    __nv_bfloat16 *xh, *xl, *Qh, *Ql, *Kh, *Kl, *Vth, *Vtl, *Ph, *Pl, *AOh, *AOl;
    __nv_bfloat16 *wqh, *wql, *wkh, *wkl, *wvh, *wvl, *woh, *wol;
    cudaGetSymbolAddress((void**)&Qp, g_Q);
    cudaGetSymbolAddress((void**)&Kp, g_K);
    cudaGetSymbolAddress((void**)&AOp, g_AO);
    cudaGetSymbolAddress((void**)&Sc, g_scores);
    cudaGetSymbolAddress((void**)&akp, g_ak);
    cudaGetSymbolAddress((void**)&avp, g_av);
    cudaGetSymbolAddress((void**)&xh, g_xh);
    cudaGetSymbolAddress((void**)&xl, g_xl);
    cudaGetSymbolAddress((void**)&Qh, g_Qh);
    cudaGetSymbolAddress((void**)&Ql, g_Ql);
    cudaGetSymbolAddress((void**)&Kh, g_Kh);
    cudaGetSymbolAddress((void**)&Kl, g_Kl);
    cudaGetSymbolAddress((void**)&Vth, g_Vth);
    cudaGetSymbolAddress((void**)&Vtl, g_Vtl);
    cudaGetSymbolAddress((void**)&Ph, g_Ph);
    cudaGetSymbolAddress((void**)&Pl, g_Pl);
    cudaGetSymbolAddress((void**)&AOh, g_AOh);
    cudaGetSymbolAddress((void**)&AOl, g_AOl);
    cudaGetSymbolAddress((void**)&wqh, g_wqh);
    cudaGetSymbolAddress((void**)&wql, g_wql);
    cudaGetSymbolAddress((void**)&wkh, g_wkh);
    cudaGetSymbolAddress((void**)&wkl, g_wkl);
    cudaGetSymbolAddress((void**)&wvh, g_wvh);
    cudaGetSymbolAddress((void**)&wvl, g_wvl);
    cudaGetSymbolAddress((void**)&woh, g_woh);
    cudaGetSymbolAddress((void**)&wol, g_wol);

    const float inv_sqrt = 0.08838834764831845f;
    const long long NTOK = (long long)NB * NS;          // 4096
    const long long NELT = NTOK * ND;                   // 16M
    const int SMEMB = 3 * 64 * (128 + 256);             // 73728 bytes

    // Raise dynamic-smem limits (host-side attribute set; idempotent,
    // not a stream op -> graph-capture safe)
    cudaFuncSetAttribute(mma_gemm<128, 256, 4, 0>,
                         cudaFuncAttributeMaxDynamicSharedMemorySize, SMEMB);
    cudaFuncSetAttribute(mma_gemm<128, 256, 4, 1>,
                         cudaFuncAttributeMaxDynamicSharedMemorySize, SMEMB);
    cudaFuncSetAttribute(mma_gemm<128, 256, 4, 2>,
                         cudaFuncAttributeMaxDynamicSharedMemorySize, SMEMB);
    cudaFuncSetAttribute(mma_gemm<256, 128, 2, 0>,
                         cudaFuncAttributeMaxDynamicSharedMemorySize, SMEMB);

    // 0. Split x; transpose+split weights
    split_kernel<<<(unsigned)(NELT / 1024), 256>>>(x, xh, xl, NELT);
    {
        dim3 g(ND / 32, ND / 32), b(32, 8);
        wsplit_t_kernel<<<g, b>>>(wq, wqh, wql);
        wsplit_t_kernel<<<g, b>>>(wk, wkh, wkl);
        wsplit_t_kernel<<<g, b>>>(wv, wvh, wvl);
        wsplit_t_kernel<<<g, b>>>(wo, woh, wol);
    }

    // 1-3. Projections (M=4096, N=4096, K=4096), CTA tile 128x256
    {
        dim3 g(ND / 256, (unsigned)(NTOK / 128), 1);
        mma_gemm<128, 256, 4, 0><<<g, 256, SMEMB>>>(
            xh, xl, wqh, wql, Qp, ND, ND, ND, ND, 1,
            0, 0, 0, 0, 0, 0, 1.f, nullptr, nullptr, nullptr);
        mma_gemm<128, 256, 4, 0><<<g, 256, SMEMB>>>(
            xh, xl, wkh, wkl, Kp, ND, ND, ND, ND, 1,
            0, 0, 0, 0, 0, 0, 1.f, nullptr, nullptr, nullptr);
        mma_gemm<128, 256, 4, 2><<<g, 256, SMEMB>>>(
            xh, xl, wvh, wvl, nullptr, ND, ND, ND, ND, 1,
            0, 0, 0, 0, 0, 0, 1.f, nullptr, Vth, Vtl);
    }

    // 4. RoPE
    {
        const long long total = (long long)NB * NS * NH * (NHD / 2);
        rope_qk_kernel<<<(unsigned)((total + 255) / 256), 256>>>(
            Qp, Kp, cosT, sinT, Qh, Ql, Kh, Kl);
    }

    // 5. Adapter projections
    adapter_gemm_kernel<<<ND / 256, 256>>>(adapter, wk, wv, akp, avp);

    // 6. Scores = Q K^T * inv_sqrt + mask  (per (b,h): M=N=2048, K=128)
    {
        dim3 g(NS / 256, NS / 128, NB * NH);
        mma_gemm<128, 256, 4, 1><<<g, 256, SMEMB>>>(
            Qh, Ql, Kh, Kl, Sc, NHD, ND, ND, NS, NH,
            (long long)NS * ND, (long long)NHD,
            (long long)NS * ND, (long long)NHD,
            (long long)NH * NS * NS, (long long)NS * NS,
            inv_sqrt, mask, nullptr, nullptr);
    }

    // 7. Softmax -> bf16 hi/lo P
    softmax_rows_kernel<<<NB * NH * NS, 256>>>(Sc, Ph, Pl);

    // 8. AO = P @ V  (per (b,h): M=2048, N=128, K=2048), CTA tile 256x128
    {
        dim3 g(NHD / 128, NS / 256, NB * NH);
        mma_gemm<256, 128, 2, 0><<<g, 256, SMEMB>>>(
            Ph, Pl, Vth, Vtl, AOp, NS, NS, NS, ND, NH,
            (long long)NH * NS * NS, (long long)NS * NS,
            (long long)NH * NHD * NS, (long long)NHD * NS,
            (long long)NS * ND, (long long)NHD,
            1.f, nullptr, nullptr, nullptr);
    }

    // 9. Adapter attention add
    adapter_attn_kernel<<<dim3(NS / 8, NH, NB), 256>>>(AOp, Qp, akp, avp, gate);

    // 10. Split AO; out = AO @ wo
    split_kernel<<<(unsigned)(NELT / 1024), 256>>>(AOp, AOh, AOl, NELT);
    {
        dim3 g(ND / 256, (unsigned)(NTOK / 128), 1);
        mma_gemm<128, 256, 4, 0><<<g, 256, SMEMB>>>(
            AOh, AOl, woh, wol, out, ND, ND, ND, ND, 1,
            0, 0, 0, 0, 0, 0, 1.f, nullptr, nullptr, nullptr);
    }
}